// round 16
// baseline (speedup 1.0000x reference)
#include <cuda_runtime.h>
#include <cuda_bf16.h>
#include <cstdint>

// FastGaussian2D: tile-binned 2D gaussian splat render, SINGLE fused kernel.
// P pixels (256x256 = 512 tiles of 16x8), N=2048 gaussians.
// out[p] = clip(sum_n alpha*color / max(sum alpha,1e-8), 0, 1)
//
// R16: bin + render fused into ONE launch with a software global barrier.
// All 512 blocks are co-resident (512 <= 148 SMs x 4 CTAs via launch_bounds;
// 40KB smem x 4 = 160KB <= 228KB), so a spin barrier is deadlock-free.
//   Phase A: warps 0-3 of block b bin gaussians {b, 512+b, 1024+b, 1536+b}
//            (4 active warps per block -> perfectly balanced).
//   Barrier: threadfence + per-block arrive on g_bar; spin until 512.
//            Replay-safe reset: each block increments g_bar again after the
//            spin; the block seeing old==1023 (everyone passed) resets to 0.
//   Phase B: render, identical to R15 (warp-private cp.async staging,
//            separable exponential, f32x2 accumulate, block reduction,
//            direct finalize into d_out; re-zeroes tile counter for replay).
//
// Cull safety: dropped per-pixel alpha <= ~1.2e-6 absolute vs total alpha
// >= ~1e-2 -> relative impact ~1e-4, below the 1e-3 gate with margin.

#define IMG_W 256
#define TILE_W 16
#define TILE_H 8
#define NTILES_X 16
#define NTILES_Y 32
#define NTILES 512
#define MAX_N 2048
#define WIN 32
#define LOG2E 1.4426950408889634f
#define PI_F  3.14159265358979323846f
#define THR_LOG2 -28.0f

typedef unsigned long long ull;

__device__ int        g_bar;                     // global barrier; 0 at every replay
__device__ int        g_counts[NTILES];          // zero-init; re-zeroed by render
__device__ float4     gA  [NTILES * MAX_N];      // {px, py, naxl, nayl}
__device__ ulonglong2 gW12[NTILES * MAX_N];      // {(wr,wr), (wg,wg)}
__device__ ulonglong2 gW34[NTILES * MAX_N];      // {(wb,wb), (wa,wa)}

__device__ __forceinline__ ull packf(float a, float b) {
    return (ull)__float_as_uint(a) | ((ull)__float_as_uint(b) << 32);
}
__device__ __forceinline__ float lowf(ull v)  { return __uint_as_float((unsigned)v); }
__device__ __forceinline__ float highf(ull v) { return __uint_as_float((unsigned)(v >> 32)); }

__device__ __forceinline__ ull mul2(ull a, ull b) {
    ull d; asm("mul.rn.f32x2 %0, %1, %2;" : "=l"(d) : "l"(a), "l"(b)); return d;
}
__device__ __forceinline__ ull fma2(ull a, ull b, ull c) {
    ull d; asm("fma.rn.f32x2 %0, %1, %2, %3;" : "=l"(d) : "l"(a), "l"(b), "l"(c)); return d;
}
__device__ __forceinline__ float ex2f(float x) {
    float y; asm("ex2.approx.ftz.f32 %0, %1;" : "=f"(y) : "f"(x)); return y;
}
__device__ __forceinline__ uint32_t s2u(const void* p) {
    return (uint32_t)__cvta_generic_to_shared(p);
}
__device__ __forceinline__ void cpa16(uint32_t dst, const void* src) {
    asm volatile("cp.async.ca.shared.global [%0], [%1], 16;" :: "r"(dst), "l"(src));
}

// ---------------------------------------------------------------- fused kernel
__global__ void __launch_bounds__(256, 4)
fg_fused(const float* __restrict__ pos,
         const float* __restrict__ lsc,
         const float* __restrict__ col,
         const float* __restrict__ lop,
         float* __restrict__ out, int N, int P) {
    __shared__ float4     sA  [8][2][WIN];   //  8 KB
    __shared__ ulonglong2 sW12[8][2][WIN];   //  8 KB
    __shared__ ulonglong2 sW34[8][2][WIN];   //  8 KB
    __shared__ float      sred[8 * 512];     // 16 KB

    const int tile = blockIdx.x;
    const int warp = threadIdx.x >> 5;
    const int lane = threadIdx.x & 31;
    const int tid  = threadIdx.x;

    // ================= Phase A: bin (warps 0-3; gaussian = warp*512 + block)
    if (warp < 4) {
        const int g = warp * NTILES + blockIdx.x;
        if (g < N) {
            const float px = pos[2*g], py = pos[2*g+1];
            const float sx = fmaxf(expf(lsc[2*g]),   0.1f);
            const float sy = fmaxf(expf(lsc[2*g+1]), 0.1f);
            const float opac = expf(lop[g]);
            const float c = opac / (2.0f * PI_F * sx * sy);
            const float naxl = -0.5f * LOG2E / (sx * sx);
            const float nayl = -0.5f * LOG2E / (sy * sy);

            const float4 A = make_float4(px, py, naxl, nayl);
            const float wr = c * col[3*g], wg = c * col[3*g+1], wb = c * col[3*g+2];
            const ulonglong2 W12 = make_ulonglong2(packf(wr, wr), packf(wg, wg));
            const ulonglong2 W34 = make_ulonglong2(packf(wb, wb), packf(c,  c));

            const float rx = sqrtf(THR_LOG2 / naxl);
            const float ry = sqrtf(THR_LOG2 / nayl);

            int tx0 = max(0,            (int)floorf((px - rx) * (1.0f/TILE_W)));
            int tx1 = min(NTILES_X - 1, (int)floorf((px + rx) * (1.0f/TILE_W)));
            int ty0 = max(0,            (int)floorf((py - ry) * (1.0f/TILE_H)));
            int ty1 = min(NTILES_Y - 1, (int)floorf((py + ry) * (1.0f/TILE_H)));
            if (tx1 >= tx0 && ty1 >= ty0) {
                const int wbb = tx1 - tx0 + 1;
                const int nt  = wbb * (ty1 - ty0 + 1);
                for (int i = lane; i < nt; i += 32) {
                    const int tx = tx0 + i % wbb;
                    const int ty = ty0 + i / wbb;
                    const float mx = fmaxf(fabsf((float)(tx * TILE_W) + 7.5f - px) - 7.5f, 0.0f);
                    const float my = fmaxf(fabsf((float)(ty * TILE_H) + 3.5f - py) - 3.5f, 0.0f);
                    if (naxl * (mx * mx) + nayl * (my * my) >= THR_LOG2) {
                        const int t = ty * NTILES_X + tx;
                        const int slot = atomicAdd(&g_counts[t], 1);   // slot < N
                        const int idx = t * MAX_N + slot;
                        gA  [idx] = A;
                        gW12[idx] = W12;
                        gW34[idx] = W34;
                    }
                }
            }
        }
    }

    // ================= global barrier (all 512 blocks co-resident)
    __syncthreads();
    __threadfence();
    if (tid == 0) {
        atomicAdd(&g_bar, 1);
        while (*(volatile int*)&g_bar < NTILES) { }
        // replay-safe reset: second pass; last block to pass resets to 0
        const int old = atomicAdd(&g_bar, 1);
        if (old == 2 * NTILES - 1) *(volatile int*)&g_bar = 0;
    }
    __syncthreads();
    __threadfence();

    // ================= Phase B: render (identical to R15)
    const int x0 = (tile & (NTILES_X - 1)) * TILE_W;
    const int y0 = (tile >> 4) * TILE_H;

    const bool isX  = (lane < 16);
    const float u   = isX ? (float)(x0 + lane) : (float)(y0 + (lane & 7));
    const int rowSh = 16 + (lane >> 2);
    const int xg4   = (lane & 3) * 4;

    const int count = g_counts[tile];
    const int base  = tile * MAX_N;

    __syncthreads();                       // everyone has read count
    if (tid == 0) g_counts[tile] = 0;      // restore invariant for next replay

    const int s0   = (count *  warp     ) >> 3;
    const int s1   = (count * (warp + 1)) >> 3;
    const int len  = s1 - s0;
    const int nwin = (len + WIN - 1) / WIN;
    const int gb0  = base + s0;

    auto copy_win = [&](int b, int w) {
        const int e = w * WIN + lane;
        if (e < len) {
            cpa16(s2u(&sA  [warp][b][lane]), &gA  [gb0 + e]);
            cpa16(s2u(&sW12[warp][b][lane]), &gW12[gb0 + e]);
            cpa16(s2u(&sW34[warp][b][lane]), &gW34[gb0 + e]);
        }
        asm volatile("cp.async.commit_group;");
    };

    ull aR0 = 0, aR1 = 0, aG0 = 0, aG1 = 0;
    ull aB0 = 0, aB1 = 0, aA0 = 0, aA1 = 0;

    if (nwin > 0) copy_win(0, 0);

    for (int w = 0; w < nwin; ++w) {
        const int b = w & 1;
        if (w + 1 < nwin) {
            copy_win((w + 1) & 1, w + 1);
            asm volatile("cp.async.wait_group 1;");
        } else {
            asm volatile("cp.async.wait_group 0;");
        }
        __syncwarp();

        const int wsz = min(WIN, len - w * WIN);
        #pragma unroll 4
        for (int k = 0; k < wsz; ++k) {
            const float4 A = sA[warp][b][k];

            const float ctr  = isX ? A.x : A.y;
            const float coef = isX ? A.z : A.w;
            const float d    = u - ctr;
            const float v    = ex2f(coef * (d * d));

            const float ey = __shfl_sync(0xFFFFFFFFu, v, rowSh);
            const float e0 = __shfl_sync(0xFFFFFFFFu, v, xg4 + 0);
            const float e1 = __shfl_sync(0xFFFFFFFFu, v, xg4 + 1);
            const float e2 = __shfl_sync(0xFFFFFFFFu, v, xg4 + 2);
            const float e3 = __shfl_sync(0xFFFFFFFFu, v, xg4 + 3);

            const ull ey2v = packf(ey, ey);
            const ull exy0 = mul2(packf(e0, e1), ey2v);
            const ull exy1 = mul2(packf(e2, e3), ey2v);

            const ulonglong2 w12 = sW12[warp][b][k];
            const ulonglong2 w34 = sW34[warp][b][k];

            aR0 = fma2(exy0, w12.x, aR0);  aR1 = fma2(exy1, w12.x, aR1);
            aG0 = fma2(exy0, w12.y, aG0);  aG1 = fma2(exy1, w12.y, aG1);
            aB0 = fma2(exy0, w34.x, aB0);  aB1 = fma2(exy1, w34.x, aB1);
            aA0 = fma2(exy0, w34.y, aA0);  aA1 = fma2(exy1, w34.y, aA1);
        }
        __syncwarp();
    }

    float vals[16];
    vals[ 0] = lowf(aR0); vals[ 1] = highf(aR0); vals[ 2] = lowf(aR1); vals[ 3] = highf(aR1);
    vals[ 4] = lowf(aG0); vals[ 5] = highf(aG0); vals[ 6] = lowf(aG1); vals[ 7] = highf(aG1);
    vals[ 8] = lowf(aB0); vals[ 9] = highf(aB0); vals[10] = lowf(aB1); vals[11] = highf(aB1);
    vals[12] = lowf(aA0); vals[13] = highf(aA0); vals[14] = lowf(aA1); vals[15] = highf(aA1);

    float* dst = &sred[warp * 512 + lane * 16];
    #pragma unroll
    for (int k = 0; k < 16; ++k) dst[k] = vals[k];
    __syncthreads();

    const int i0 = tid;
    const int i1 = tid + 256;
    float s0r = 0.f, s1r = 0.f;
    #pragma unroll
    for (int w = 0; w < 8; ++w) {
        s0r += sred[w * 512 + i0];
        s1r += sred[w * 512 + i1];
    }
    __syncthreads();
    sred[i0] = s0r;
    sred[i1] = s1r;
    __syncthreads();

    if (tid < 128) {
        const int p = tid;                // = l*4 + j
        const int l = p >> 2;
        const int j = p & 3;
        const float r = sred[l * 16 +  0 + j];
        const float g = sred[l * 16 +  4 + j];
        const float b = sred[l * 16 +  8 + j];
        const float a = sred[l * 16 + 12 + j];
        const float inv = 1.0f / fmaxf(a, 1e-8f);
        const int ppx = x0 + (l & 3) * 4 + j;
        const int ppy = y0 + (l >> 2);
        const int pp  = ppy * IMG_W + ppx;
        if (pp < P) {
            out[3*pp + 0] = __saturatef(r * inv);
            out[3*pp + 1] = __saturatef(g * inv);
            out[3*pp + 2] = __saturatef(b * inv);
        }
    }
}

// ---------------------------------------------------------------- launch
extern "C" void kernel_launch(void* const* d_in, const int* in_sizes, int n_in,
                              void* d_out, int out_size) {
    const float* pos = (const float*)d_in[1];
    const float* lsc = (const float*)d_in[2];
    const float* col = (const float*)d_in[3];
    const float* lop = (const float*)d_in[4];
    float* out = (float*)d_out;

    int N = in_sizes[1] / 2;
    int P = out_size / 3;
    if (N > MAX_N) N = MAX_N;

    fg_fused<<<NTILES, 256>>>(pos, lsc, col, lop, out, N, P);
}